// round 8
// baseline (speedup 1.0000x reference)
#include <cuda_runtime.h>

#define B_ 32
#define Q_ 16
#define K_ 4096
#define D_ 128
#define V_ 128
#define THREADS 64         /* 2 warps per block */
#define NWARP 2
#define GRID 1024          /* 2048 warps x 64 keys */
#define KW 64              /* keys per warp */
#define TK 16              /* keys per tile/chunk */
#define NT 64              /* tiles per warp = 4 chunks x 16 q */
#define SCALE 0.08838834764831845f  /* 1/sqrt(128) */

// scratch for attn if harness only validates `output`
__device__ float g_attn_scratch[(size_t)B_ * Q_ * K_];

__device__ __forceinline__ void red_add_v4(float* p, float4 v) {
    asm volatile("red.global.add.v4.f32 [%0], {%1,%2,%3,%4};"
                 :: "l"(p), "f"(v.x), "f"(v.y), "f"(v.z), "f"(v.w) : "memory");
}
__device__ __forceinline__ void cp_async16(void* smem_dst, const void* gsrc) {
    unsigned s = (unsigned)__cvta_generic_to_shared(smem_dst);
    asm volatile("cp.async.cg.shared.global [%0], [%1], 16;" :: "r"(s), "l"(gsrc));
}
__device__ __forceinline__ void cp_async_commit() { asm volatile("cp.async.commit_group;"); }
__device__ __forceinline__ void cp_async_wait0() { asm volatile("cp.async.wait_group 0;"); }
__device__ __forceinline__ void cp_async_wait1() { asm volatile("cp.async.wait_group 1;"); }

__global__ __launch_bounds__(THREADS, 6)
void inv_attn_kernel(const float4* __restrict__ query4,
                     const float4* __restrict__ key4,
                     const float4* __restrict__ value4,
                     float* __restrict__ out,       // [B,Q,V] pre-zeroed, RED-accumulated
                     float* __restrict__ attn_out)  // [B,Q,K]
{
    __shared__ float4 kbuf[NWARP][2][TK][32];   // 32 KB: double-buffered key tiles
    __shared__ float  att[NWARP][Q_][TK];       // 2 KB

    const int warp = threadIdx.x >> 5;
    const int lane = threadIdx.x & 31;
    const int gw   = blockIdx.x * NWARP + warp;   // 0..2047
    const int b    = gw >> 6;                     // 64 warps per batch
    const int kbase = (gw & 63) * KW;

    float4 acc[Q_];
    #pragma unroll
    for (int q = 0; q < Q_; q++) acc[q] = make_float4(0.f, 0.f, 0.f, 0.f);

    // ---- prefetch tile 0 (chunk 0, q 0) ----
    {
        const float4* src =
            key4 + ((size_t)(b * Q_ + 0) * K_ + kbase) * 32 + lane;
        #pragma unroll
        for (int r = 0; r < TK; r++)
            cp_async16(&kbuf[warp][0][r][lane], src + r * 32);
        cp_async_commit();
    }

    #pragma unroll 1
    for (int c = 0; c < KW / TK; c++) {
        const int k0 = kbase + c * TK;

        // ---- ph1: logits for 16 keys x 16 q, pipelined key tiles ----
        #pragma unroll 1
        for (int q = 0; q < Q_; q++) {
            const int t  = c * TK + q;   // tile id (chunk-major, q-minor)
            const int nt = t + 1;
            if (nt < NT) {
                const int nc = nt >> 4, nq = nt & 15;
                const float4* src =
                    key4 + ((size_t)(b * Q_ + nq) * K_ + kbase + nc * TK) * 32 + lane;
                #pragma unroll
                for (int r = 0; r < TK; r++)
                    cp_async16(&kbuf[warp][nt & 1][r][lane], src + r * 32);
                cp_async_commit();
                cp_async_wait1();       // tile t complete, t+1 in flight
            } else {
                cp_async_wait0();
            }

            float4 qv = __ldg(query4 + (b * Q_ + q) * (D_ / 4) + lane);
            qv.x *= SCALE; qv.y *= SCALE; qv.z *= SCALE; qv.w *= SCALE;
            const float4* kb = &kbuf[warp][t & 1][0][lane];
            #pragma unroll
            for (int kk = 0; kk < TK; kk++) {
                float4 kv = kb[kk * 32];            // self-deposited bytes, no sync needed
                float p = qv.x * kv.x + qv.y * kv.y + qv.z * kv.z + qv.w * kv.w;
                p += __shfl_xor_sync(0xffffffffu, p, 16);
                p += __shfl_xor_sync(0xffffffffu, p, 8);
                p += __shfl_xor_sync(0xffffffffu, p, 4);
                p += __shfl_xor_sync(0xffffffffu, p, 2);
                p += __shfl_xor_sync(0xffffffffu, p, 1);
                if (lane == 0) att[warp][q][kk] = p;
            }
        }
        __syncwarp();

        // ---- ph2: softmax over q; lane < TK owns key k0+lane ----
        if (lane < TK) {
            float l[Q_];
            float mx = -1e30f;
            #pragma unroll
            for (int q = 0; q < Q_; q++) { l[q] = att[warp][q][lane]; mx = fmaxf(mx, l[q]); }
            float s = 0.0f;
            #pragma unroll
            for (int q = 0; q < Q_; q++) { l[q] = __expf(l[q] - mx); s += l[q]; }
            float inv = 1.0f / s;
            #pragma unroll
            for (int q = 0; q < Q_; q++) {
                float a = l[q] * inv;
                att[warp][q][lane] = a;
                __stcs(&attn_out[(size_t)(b * Q_ + q) * K_ + k0 + lane], a);
            }
        }
        __syncwarp();

        // ---- ph3: acc[q] += att[q][kk] * value[k0+kk][lane*4..+4] ----
        // (direct batched value loads also fill the chunk-boundary DRAM window)
        #pragma unroll 1
        for (int kk = 0; kk < TK; kk += 4) {
            const float4* vp =
                value4 + ((size_t)b * K_ + k0 + kk) * (V_ / 4) + lane;
            float4 v0 = __ldcs(vp);
            float4 v1 = __ldcs(vp + 32);
            float4 v2 = __ldcs(vp + 64);
            float4 v3 = __ldcs(vp + 96);
            #pragma unroll
            for (int q = 0; q < Q_; q++) {
                float4 a4 = *reinterpret_cast<const float4*>(&att[warp][q][kk]);
                acc[q].x += a4.x * v0.x + a4.y * v1.x + a4.z * v2.x + a4.w * v3.x;
                acc[q].y += a4.x * v0.y + a4.y * v1.y + a4.z * v2.y + a4.w * v3.y;
                acc[q].z += a4.x * v0.z + a4.y * v1.z + a4.z * v2.z + a4.w * v3.z;
                acc[q].w += a4.x * v0.w + a4.y * v1.w + a4.z * v2.w + a4.w * v3.w;
            }
        }
        __syncwarp();   // att reused next chunk
    }

    // ---- flush: one RED.v4 per q per lane ----
    float* o = out + (size_t)b * Q_ * V_ + lane * 4;
    #pragma unroll
    for (int q = 0; q < Q_; q++)
        red_add_v4(o + (size_t)q * V_, acc[q]);
}

extern "C" void kernel_launch(void* const* d_in, const int* in_sizes, int n_in,
                              void* d_out, int out_size)
{
    const float4* query = (const float4*)d_in[0];
    const float4* key   = (const float4*)d_in[1];
    const float4* value = (const float4*)d_in[2];

    float* out = (float*)d_out;
    float* attn;
    const int out_elems  = B_ * Q_ * V_;        // 65536
    const int attn_elems = B_ * Q_ * K_;        // 2097152

    if (out_size >= out_elems + attn_elems) {
        attn = out + out_elems;                 // (output, attn) concatenated
    } else {
        cudaGetSymbolAddress((void**)&attn, g_attn_scratch);
    }

    cudaMemsetAsync(d_out, 0, (size_t)out_elems * sizeof(float));

    inv_attn_kernel<<<GRID, THREADS>>>(query, key, value, out, attn);
}

// round 9
// speedup vs baseline: 1.7583x; 1.7583x over previous
#include <cuda_runtime.h>

#define B_ 32
#define Q_ 16
#define K_ 4096
#define D_ 128
#define V_ 128
#define THREADS 128        /* 4 warps per block */
#define NWARP 4
#define GRID 512           /* 2048 warps x 64 keys */
#define KW 64
#define CHUNK 16           /* keys per chunk; 4 chunks per warp */
#define NCH (KW / CHUNK)
#define NPF 4              /* q-regions of next chunk to L2-prefetch */
#define SCALE 0.08838834764831845f  /* 1/sqrt(128) */

// scratch for attn if harness only validates `output`
__device__ float g_attn_scratch[(size_t)B_ * Q_ * K_];

__device__ __forceinline__ void red_add_v4(float* p, float4 v) {
    asm volatile("red.global.add.v4.f32 [%0], {%1,%2,%3,%4};"
                 :: "l"(p), "f"(v.x), "f"(v.y), "f"(v.z), "f"(v.w) : "memory");
}
__device__ __forceinline__ void cp_async16(void* smem_dst, const void* gsrc) {
    unsigned s = (unsigned)__cvta_generic_to_shared(smem_dst);
    asm volatile("cp.async.cg.shared.global [%0], [%1], 16;" :: "r"(s), "l"(gsrc));
}
__device__ __forceinline__ void cp_async_commit() { asm volatile("cp.async.commit_group;"); }
__device__ __forceinline__ void cp_async_wait0() { asm volatile("cp.async.wait_group 0;"); }
__device__ __forceinline__ void prefetch_l2(const void* g, unsigned bytes) {
    asm volatile("cp.async.bulk.prefetch.L2.global [%0], %1;" :: "l"(g), "r"(bytes));
}

__global__ __launch_bounds__(THREADS, 4)
void inv_attn_kernel(const float4* __restrict__ query4,
                     const float4* __restrict__ key4,
                     const float4* __restrict__ value4,
                     float* __restrict__ out,       // [B,Q,V] pre-zeroed, RED-accumulated
                     float* __restrict__ attn_out)  // [B,Q,K]
{
    __shared__ float  att[NWARP][Q_][CHUNK];       // 4 KB
    __shared__ float4 vt[NWARP][CHUNK][V_ / 4];    // 32 KB value staging

    const int warp = threadIdx.x >> 5;
    const int lane = threadIdx.x & 31;
    const int gw   = blockIdx.x * NWARP + warp;    // 0..2047
    const int b    = gw >> 6;                      // 64 warps per batch
    const int kbase = (gw & 63) * KW;

    float4 acc[Q_];
    #pragma unroll
    for (int q = 0; q < Q_; q++) acc[q] = make_float4(0.f, 0.f, 0.f, 0.f);

    #pragma unroll 1
    for (int c = 0; c < NCH; c++) {
        const int k0 = kbase + c * CHUNK;

        // ---- stage this chunk's value rows (lands under ph1) ----
        const float4* vp = value4 + ((size_t)b * K_ + k0) * (V_ / 4) + lane;
        #pragma unroll
        for (int r = 0; r < CHUNK; r++)
            cp_async16(&vt[warp][r][lane], vp + r * 32);
        cp_async_commit();

        // ---- ph1: logits; 16 q x 16 keys, batched LDG.128 (R5 engine) ----
        #pragma unroll 1
        for (int q = 0; q < Q_; q++) {
            float4 qv = __ldg(query4 + (b * Q_ + q) * (D_ / 4) + lane);
            qv.x *= SCALE; qv.y *= SCALE; qv.z *= SCALE; qv.w *= SCALE;
            const float4* kp =
                key4 + ((size_t)(b * Q_ + q) * K_ + k0) * (D_ / 4);
            #pragma unroll 8
            for (int kk = 0; kk < CHUNK; kk++) {
                float4 kv = __ldcs(kp + kk * 32 + lane);   // 512B coalesced row
                float p = qv.x * kv.x + qv.y * kv.y + qv.z * kv.z + qv.w * kv.w;
                p += __shfl_xor_sync(0xffffffffu, p, 16);
                p += __shfl_xor_sync(0xffffffffu, p, 8);
                p += __shfl_xor_sync(0xffffffffu, p, 4);
                p += __shfl_xor_sync(0xffffffffu, p, 2);
                p += __shfl_xor_sync(0xffffffffu, p, 1);
                if (lane == 0) att[warp][q][kk] = p;
            }
        }

        // ---- fill the ph2/ph3 DRAM hole: L2 bulk-prefetch next chunk ----
        if (c + 1 < NCH && lane == 0) {
            const int kn = k0 + CHUNK;
            #pragma unroll
            for (int nq = 0; nq < NPF; nq++)
                prefetch_l2(key4 + ((size_t)(b * Q_ + nq) * K_ + kn) * (D_ / 4),
                            CHUNK * D_ * 4);                 // 8 KB keys, query nq
            prefetch_l2(value4 + ((size_t)b * K_ + kn) * (V_ / 4),
                        CHUNK * V_ * 4);                     // 8 KB value
        }
        __syncwarp();

        // ---- ph2: softmax over q; lane < CHUNK owns key k0+lane ----
        if (lane < CHUNK) {
            float l[Q_];
            float mx = -1e30f;
            #pragma unroll
            for (int q = 0; q < Q_; q++) { l[q] = att[warp][q][lane]; mx = fmaxf(mx, l[q]); }
            float s = 0.0f;
            #pragma unroll
            for (int q = 0; q < Q_; q++) { l[q] = __expf(l[q] - mx); s += l[q]; }
            float inv = 1.0f / s;
            #pragma unroll
            for (int q = 0; q < Q_; q++) {
                float a = l[q] * inv;
                att[warp][q][lane] = a;
                __stcs(&attn_out[(size_t)(b * Q_ + q) * K_ + k0 + lane], a);
            }
        }
        __syncwarp();

        // ---- ph3: acc[q] += att[q][kk] * vt[kk][lane] ----
        cp_async_wait0();
        __syncwarp();
        #pragma unroll 4
        for (int kk = 0; kk < CHUNK; kk += 4) {
            float4 v0 = vt[warp][kk + 0][lane];
            float4 v1 = vt[warp][kk + 1][lane];
            float4 v2 = vt[warp][kk + 2][lane];
            float4 v3 = vt[warp][kk + 3][lane];
            #pragma unroll
            for (int q = 0; q < Q_; q++) {
                float4 a4 = *reinterpret_cast<const float4*>(&att[warp][q][kk]);
                acc[q].x += a4.x * v0.x + a4.y * v1.x + a4.z * v2.x + a4.w * v3.x;
                acc[q].y += a4.x * v0.y + a4.y * v1.y + a4.z * v2.y + a4.w * v3.y;
                acc[q].z += a4.x * v0.z + a4.y * v1.z + a4.z * v2.z + a4.w * v3.z;
                acc[q].w += a4.x * v0.w + a4.y * v1.w + a4.z * v2.w + a4.w * v3.w;
            }
        }
        __syncwarp();   // att + vt reused next chunk
    }

    // ---- flush: one RED.v4 per q per lane ----
    float* o = out + (size_t)b * Q_ * V_ + lane * 4;
    #pragma unroll
    for (int q = 0; q < Q_; q++)
        red_add_v4(o + (size_t)q * V_, acc[q]);
}

extern "C" void kernel_launch(void* const* d_in, const int* in_sizes, int n_in,
                              void* d_out, int out_size)
{
    const float4* query = (const float4*)d_in[0];
    const float4* key   = (const float4*)d_in[1];
    const float4* value = (const float4*)d_in[2];

    float* out = (float*)d_out;
    float* attn;
    const int out_elems  = B_ * Q_ * V_;        // 65536
    const int attn_elems = B_ * Q_ * K_;        // 2097152

    if (out_size >= out_elems + attn_elems) {
        attn = out + out_elems;                 // (output, attn) concatenated
    } else {
        cudaGetSymbolAddress((void**)&attn, g_attn_scratch);
    }

    cudaMemsetAsync(d_out, 0, (size_t)out_elems * sizeof(float));

    inv_attn_kernel<<<GRID, THREADS>>>(query, key, value, out, attn);
}